// round 6
// baseline (speedup 1.0000x reference)
#include <cuda_runtime.h>
#include <cuda_bf16.h>
#include <math.h>

#define BB 64
#define TT 1024
#define MAXLAG 256
#define THREADS1 512

// Scratch (device globals — no allocation allowed).
__device__ float g_S[BB * MAXLAG];   // per-(batch,lag) sum of squared displacements
__device__ float g_P[BB];            // per-batch loss
__device__ int   g_cnt[BB];          // per-batch arrival counters (self-resetting)
__device__ int   g_done = 0;         // global finalize counter (self-resetting)

// Fused kernel. grid = (64 batches, 4 lag-phases), 512 threads (16 warps).
// Block (b,y): lags lag = 4w + y + 1 + 64j  (w=0..15, j=0..3)  — stride-4
// interleave so all 4 blocks of a batch have equal work. Warp w reuses the
// start point s[p] across its 4 lags.
// Tail: last block of batch b fits that batch; globally-last block reduces.
__global__ __launch_bounds__(THREADS1) void physics_kernel(
    const float* __restrict__ traj,
    const float* __restrict__ alpha_pred,
    const int* __restrict__ lengths,
    float* __restrict__ out)
{
    __shared__ float2 s[TT];
    __shared__ float sh[16];
    __shared__ int flag_b, flag_all;

    const int b = blockIdx.x;
    const int y = blockIdx.y;
    const float2* tr = reinterpret_cast<const float2*>(traj) + (size_t)b * TT;
    for (int i = threadIdx.x; i < TT; i += THREADS1) s[i] = tr[i];
    __syncthreads();

    const int L    = lengths[b];
    const int w    = threadIdx.x >> 5;
    const int lane = threadIdx.x & 31;

    // ---- MSD phase ----
    const int lag0 = 4 * w + y + 1;            // lag_j = lag0 + 64j
    int np0 = L - lag0;            if (np0 < 0) np0 = 0;
    int np1 = np0 - 64;            if (np1 < 0) np1 = 0;
    int np2 = np0 - 128;           if (np2 < 0) np2 = 0;
    int np3 = np0 - 192;           if (np3 < 0) np3 = 0;

    float acc0 = 0.f, acc1 = 0.f, acc2 = 0.f, acc3 = 0.f;

    for (int p = lane; p < np0; p += 32) {
        const float2 a = s[p];
        {
            const float2 e = s[p + lag0];
            const float dx = e.x - a.x, dy = e.y - a.y;
            acc0 = fmaf(dx, dx, acc0); acc0 = fmaf(dy, dy, acc0);
        }
        if (p < np1) {
            const float2 e = s[p + lag0 + 64];
            const float dx = e.x - a.x, dy = e.y - a.y;
            acc1 = fmaf(dx, dx, acc1); acc1 = fmaf(dy, dy, acc1);
        }
        if (p < np2) {
            const float2 e = s[p + lag0 + 128];
            const float dx = e.x - a.x, dy = e.y - a.y;
            acc2 = fmaf(dx, dx, acc2); acc2 = fmaf(dy, dy, acc2);
        }
        if (p < np3) {
            const float2 e = s[p + lag0 + 192];
            const float dx = e.x - a.x, dy = e.y - a.y;
            acc3 = fmaf(dx, dx, acc3); acc3 = fmaf(dy, dy, acc3);
        }
    }

#pragma unroll
    for (int o = 16; o; o >>= 1) {
        acc0 += __shfl_xor_sync(0xffffffffu, acc0, o);
        acc1 += __shfl_xor_sync(0xffffffffu, acc1, o);
        acc2 += __shfl_xor_sync(0xffffffffu, acc2, o);
        acc3 += __shfl_xor_sync(0xffffffffu, acc3, o);
    }
    if (lane == 0) {
        float* dst = &g_S[b * MAXLAG + (4 * w + y)];
        dst[0]   = acc0;
        dst[64]  = acc1;
        dst[128] = acc2;
        dst[192] = acc3;
    }
    __threadfence();
    __syncthreads();

    // ---- per-batch arrival; last of the 4 blocks fits batch b ----
    if (threadIdx.x == 0)
        flag_b = (atomicAdd(&g_cnt[b], 1) == 3) ? 1 : 0;
    __syncthreads();
    if (!flag_b) return;
    __threadfence();                                  // acquire side

    const float alpha = alpha_pred[b];
    const volatile float* vS = g_S;

    float resid = 0.f, m = 0.f;
    if (threadIdx.x < MAXLAG) {
        const int il  = threadIdx.x;
        const int lag = il + 1;
        const int np  = L - lag;
        const int cnt = (np > 0) ? np : 1;            // counts = max(#valid, 1)
        const float S  = vS[b * MAXLAG + il];
        const float lm = logf(S / (float)cnt + 1e-8f);
        const float ll = logf((float)lag);
        m     = (L > lag) ? 1.f : 0.f;
        resid = lm - alpha * ll;
    }

    // reduction 1: sum(resid*m), sum(m)  (warps 8..15 contribute zeros)
    float sr = resid * m, sm = m;
#pragma unroll
    for (int o = 16; o; o >>= 1) {
        sr += __shfl_xor_sync(0xffffffffu, sr, o);
        sm += __shfl_xor_sync(0xffffffffu, sm, o);
    }
    if (lane == 0 && w < 8) { sh[w] = sr; sh[8 + w] = sm; }
    __syncthreads();
    float srt = 0.f, smt = 0.f;
#pragma unroll
    for (int k = 0; k < 8; k++) { srt += sh[k]; smt += sh[8 + k]; }

    const float denom     = (smt > 1.f) ? smt : 1.f;
    const float intercept = srt / denom;

    // reduction 2: sum((intercept - resid)^2 * m)
    const float d = (intercept - resid) * m;
    float se = d * d;
#pragma unroll
    for (int o = 16; o; o >>= 1) se += __shfl_xor_sync(0xffffffffu, se, o);
    __syncthreads();
    if (lane == 0 && w < 8) sh[w] = se;
    __syncthreads();

    if (threadIdx.x == 0) {
        float t = 0.f;
#pragma unroll
        for (int k = 0; k < 8; k++) t += sh[k];
        g_cnt[b] = 0;                       // reset for next graph replay
        g_P[b]   = t / denom;
        __threadfence();
        flag_all = (atomicAdd(&g_done, 1) == BB - 1) ? 1 : 0;
    }
    __syncthreads();
    if (!flag_all) return;

    // ---- globally-last block: mean over batches ----
    if (threadIdx.x < 32) {
        __threadfence();
        const volatile float* vp = g_P;
        float t = vp[threadIdx.x] + vp[threadIdx.x + 32];
#pragma unroll
        for (int o = 16; o; o >>= 1) t += __shfl_xor_sync(0xffffffffu, t, o);
        if (threadIdx.x == 0) {
            out[0] = t / (float)BB;
            g_done = 0;                     // reset for next graph replay
        }
    }
}

extern "C" void kernel_launch(void* const* d_in, const int* in_sizes, int n_in,
                              void* d_out, int out_size)
{
    const float* alpha_pred = (const float*)d_in[0];
    const float* trajectory = (const float*)d_in[1];
    const int*   lengths    = (const int*)d_in[2];
    float* out = (float*)d_out;

    dim3 g1(BB, 4, 1);
    physics_kernel<<<g1, THREADS1>>>(trajectory, alpha_pred, lengths, out);
}

// round 7
// speedup vs baseline: 1.0173x; 1.0173x over previous
#include <cuda_runtime.h>
#include <cuda_bf16.h>
#include <math.h>

#define BB 64
#define TT 1024
#define MAXLAG 256
#define THREADS1 1024

// Scratch (device globals — no allocation allowed).
__device__ float g_S[BB * MAXLAG];   // per-(batch,lag) sum of squared displacements
__device__ float g_P[BB];            // per-batch loss
__device__ int   g_cnt[BB];          // per-batch arrival counters (self-resetting)
__device__ int   g_done = 0;         // global finalize counter (self-resetting)

// Fused kernel. grid = (64 batches, 2), 1024 threads (32 warps) => 128 blocks,
// one wave on 148 SMs. Warp w of block (b,y) owns lag chunk c = 2w+y:
// four CONSECUTIVE lags 4c+1..4c+4 (np spread inside a warp is only 3, so the
// main loop is unguarded). Each lane processes 2 consecutive positions per
// iteration: 1 LDS.128 start + 5 LDS.64 end values cover all 8 point-pairs.
// Math uses packed fma.rn.f32x2 (dx,dy in one op).
__global__ __launch_bounds__(THREADS1) void physics_kernel(
    const float* __restrict__ traj,
    const float* __restrict__ alpha_pred,
    const int* __restrict__ lengths,
    float* __restrict__ out)
{
    __shared__ float2 s[TT];
    __shared__ float sh[16];
    __shared__ int flag_b, flag_all;

    const int b = blockIdx.x;
    const int y = blockIdx.y;
    const float2* tr = reinterpret_cast<const float2*>(traj) + (size_t)b * TT;
    for (int i = threadIdx.x; i < TT; i += THREADS1) s[i] = tr[i];
    __syncthreads();

    const int L    = lengths[b];
    const int w    = threadIdx.x >> 5;
    const int lane = threadIdx.x & 31;

    // ---- MSD phase ----
    const int c    = 2 * w + y;        // lag chunk 0..63
    const int lag0 = 4 * c + 1;        // lags lag0 .. lag0+3
    int np0 = L - lag0;      if (np0 < 0) np0 = 0;
    int np1 = np0 - 1;       if (np1 < 0) np1 = 0;
    int np2 = np0 - 2;       if (np2 < 0) np2 = 0;
    int np3 = np0 - 3;       if (np3 < 0) np3 = 0;

    unsigned int sbase = (unsigned int)__cvta_generic_to_shared(s);
    const unsigned long long NEG1 = 0xBF800000BF800000ULL; // {-1.f, -1.f}
    unsigned long long acc0 = 0, acc1 = 0, acc2 = 0, acc3 = 0;

    // Main loop: lane covers positions p0 = 2*lane + 64*t and p0+1, all 4 lags
    // unguarded. Valid iff worst case 63+64t < np3  =>  K = np3/64 iterations.
    const int K = np3 >> 6;
    unsigned int addr_a = sbase + ((unsigned)(2 * lane) << 3);
    unsigned int addr_e = addr_a + ((unsigned)lag0 << 3);
    for (int t = 0; t < K; ++t) {
        unsigned long long a0, a1, e0, e1, e2, e3, e4, d;
        asm("ld.shared.v2.b64 {%0,%1}, [%2];" : "=l"(a0), "=l"(a1) : "r"(addr_a));
        asm("ld.shared.b64 %0, [%1];"    : "=l"(e0) : "r"(addr_e));
        asm("ld.shared.b64 %0, [%1+8];"  : "=l"(e1) : "r"(addr_e));
        asm("ld.shared.b64 %0, [%1+16];" : "=l"(e2) : "r"(addr_e));
        asm("ld.shared.b64 %0, [%1+24];" : "=l"(e3) : "r"(addr_e));
        asm("ld.shared.b64 %0, [%1+32];" : "=l"(e4) : "r"(addr_e));
        // lag j pairs: (a0, e_j) and (a1, e_{j+1})
        asm("fma.rn.f32x2 %0, %1, %2, %3;" : "=l"(d) : "l"(a0), "l"(NEG1), "l"(e0));
        asm("fma.rn.f32x2 %0, %1, %1, %0;" : "+l"(acc0) : "l"(d));
        asm("fma.rn.f32x2 %0, %1, %2, %3;" : "=l"(d) : "l"(a1), "l"(NEG1), "l"(e1));
        asm("fma.rn.f32x2 %0, %1, %1, %0;" : "+l"(acc0) : "l"(d));

        asm("fma.rn.f32x2 %0, %1, %2, %3;" : "=l"(d) : "l"(a0), "l"(NEG1), "l"(e1));
        asm("fma.rn.f32x2 %0, %1, %1, %0;" : "+l"(acc1) : "l"(d));
        asm("fma.rn.f32x2 %0, %1, %2, %3;" : "=l"(d) : "l"(a1), "l"(NEG1), "l"(e2));
        asm("fma.rn.f32x2 %0, %1, %1, %0;" : "+l"(acc1) : "l"(d));

        asm("fma.rn.f32x2 %0, %1, %2, %3;" : "=l"(d) : "l"(a0), "l"(NEG1), "l"(e2));
        asm("fma.rn.f32x2 %0, %1, %1, %0;" : "+l"(acc2) : "l"(d));
        asm("fma.rn.f32x2 %0, %1, %2, %3;" : "=l"(d) : "l"(a1), "l"(NEG1), "l"(e3));
        asm("fma.rn.f32x2 %0, %1, %1, %0;" : "+l"(acc2) : "l"(d));

        asm("fma.rn.f32x2 %0, %1, %2, %3;" : "=l"(d) : "l"(a0), "l"(NEG1), "l"(e3));
        asm("fma.rn.f32x2 %0, %1, %1, %0;" : "+l"(acc3) : "l"(d));
        asm("fma.rn.f32x2 %0, %1, %2, %3;" : "=l"(d) : "l"(a1), "l"(NEG1), "l"(e4));
        asm("fma.rn.f32x2 %0, %1, %1, %0;" : "+l"(acc3) : "l"(d));

        addr_a += 512;   // 64 positions * 8 B
        addr_e += 512;
    }

    // Unpack packed accumulators (low = sum dx^2, high = sum dy^2).
    float f0 = __uint_as_float((unsigned)acc0) + __uint_as_float((unsigned)(acc0 >> 32));
    float f1 = __uint_as_float((unsigned)acc1) + __uint_as_float((unsigned)(acc1 >> 32));
    float f2 = __uint_as_float((unsigned)acc2) + __uint_as_float((unsigned)(acc2 >> 32));
    float f3 = __uint_as_float((unsigned)acc3) + __uint_as_float((unsigned)(acc3 >> 32));

    // Guarded tail: positions [64K, np0), stride 32. At most ~3 iterations.
    for (int p = (K << 6) + lane; p < np0; p += 32) {
        const float2 a = s[p];
        {
            const float2 e = s[p + lag0];
            const float dx = e.x - a.x, dy = e.y - a.y;
            f0 = fmaf(dx, dx, f0); f0 = fmaf(dy, dy, f0);
        }
        if (p < np1) {
            const float2 e = s[p + lag0 + 1];
            const float dx = e.x - a.x, dy = e.y - a.y;
            f1 = fmaf(dx, dx, f1); f1 = fmaf(dy, dy, f1);
        }
        if (p < np2) {
            const float2 e = s[p + lag0 + 2];
            const float dx = e.x - a.x, dy = e.y - a.y;
            f2 = fmaf(dx, dx, f2); f2 = fmaf(dy, dy, f2);
        }
        if (p < np3) {
            const float2 e = s[p + lag0 + 3];
            const float dx = e.x - a.x, dy = e.y - a.y;
            f3 = fmaf(dx, dx, f3); f3 = fmaf(dy, dy, f3);
        }
    }

#pragma unroll
    for (int o = 16; o; o >>= 1) {
        f0 += __shfl_xor_sync(0xffffffffu, f0, o);
        f1 += __shfl_xor_sync(0xffffffffu, f1, o);
        f2 += __shfl_xor_sync(0xffffffffu, f2, o);
        f3 += __shfl_xor_sync(0xffffffffu, f3, o);
    }
    if (lane == 0) {
        float* dst = &g_S[b * MAXLAG + 4 * c];
        dst[0] = f0; dst[1] = f1; dst[2] = f2; dst[3] = f3;
    }
    __threadfence();
    __syncthreads();

    // ---- per-batch arrival; last of the 2 blocks fits batch b ----
    if (threadIdx.x == 0)
        flag_b = (atomicAdd(&g_cnt[b], 1) == 1) ? 1 : 0;
    __syncthreads();
    if (!flag_b) return;
    __threadfence();                                  // acquire side

    const float alpha = alpha_pred[b];
    const volatile float* vS = g_S;

    float resid = 0.f, m = 0.f;
    if (threadIdx.x < MAXLAG) {
        const int il  = threadIdx.x;
        const int lag = il + 1;
        const int np  = L - lag;
        const int cnt = (np > 0) ? np : 1;            // counts = max(#valid, 1)
        const float S  = vS[b * MAXLAG + il];
        const float lm = logf(S / (float)cnt + 1e-8f);
        const float ll = logf((float)lag);
        m     = (L > lag) ? 1.f : 0.f;
        resid = lm - alpha * ll;
    }

    // reduction 1: sum(resid*m), sum(m)  (warps >= 8 contribute zeros)
    float sr = resid * m, sm = m;
#pragma unroll
    for (int o = 16; o; o >>= 1) {
        sr += __shfl_xor_sync(0xffffffffu, sr, o);
        sm += __shfl_xor_sync(0xffffffffu, sm, o);
    }
    if (lane == 0 && w < 8) { sh[w] = sr; sh[8 + w] = sm; }
    __syncthreads();
    float srt = 0.f, smt = 0.f;
#pragma unroll
    for (int k = 0; k < 8; k++) { srt += sh[k]; smt += sh[8 + k]; }

    const float denom     = (smt > 1.f) ? smt : 1.f;
    const float intercept = srt / denom;

    // reduction 2: sum((intercept - resid)^2 * m)
    const float d2 = (intercept - resid) * m;
    float se = d2 * d2;
#pragma unroll
    for (int o = 16; o; o >>= 1) se += __shfl_xor_sync(0xffffffffu, se, o);
    __syncthreads();
    if (lane == 0 && w < 8) sh[w] = se;
    __syncthreads();

    if (threadIdx.x == 0) {
        float t = 0.f;
#pragma unroll
        for (int k = 0; k < 8; k++) t += sh[k];
        g_cnt[b] = 0;                       // reset for next graph replay
        g_P[b]   = t / denom;
        __threadfence();
        flag_all = (atomicAdd(&g_done, 1) == BB - 1) ? 1 : 0;
    }
    __syncthreads();
    if (!flag_all) return;

    // ---- globally-last block: mean over batches ----
    if (threadIdx.x < 32) {
        __threadfence();
        const volatile float* vp = g_P;
        float t = vp[threadIdx.x] + vp[threadIdx.x + 32];
#pragma unroll
        for (int o = 16; o; o >>= 1) t += __shfl_xor_sync(0xffffffffu, t, o);
        if (threadIdx.x == 0) {
            out[0] = t / (float)BB;
            g_done = 0;                     // reset for next graph replay
        }
    }
}

extern "C" void kernel_launch(void* const* d_in, const int* in_sizes, int n_in,
                              void* d_out, int out_size)
{
    const float* alpha_pred = (const float*)d_in[0];
    const float* trajectory = (const float*)d_in[1];
    const int*   lengths    = (const int*)d_in[2];
    float* out = (float*)d_out;

    dim3 g1(BB, 2, 1);
    physics_kernel<<<g1, THREADS1>>>(trajectory, alpha_pred, lengths, out);
}

// round 8
// speedup vs baseline: 1.0705x; 1.0523x over previous
#include <cuda_runtime.h>
#include <cuda_bf16.h>
#include <math.h>

#define BB 64
#define TT 1024
#define MAXLAG 256
#define NT 512

// Cross-block scratch (device globals — no allocation allowed).
__device__ float g_P[BB];            // per-batch loss
__device__ int   g_done = 0;         // finalize counter (self-resetting)

// acc += (e - a)^2, packed over (x,y) via f32x2.
__device__ __forceinline__ void step2(unsigned long long &acc,
                                      unsigned long long a,
                                      unsigned long long e,
                                      unsigned long long neg1)
{
    unsigned long long d;
    asm("fma.rn.f32x2 %0, %1, %2, %3;" : "=l"(d) : "l"(a), "l"(neg1), "l"(e));
    asm("fma.rn.f32x2 %0, %1, %1, %0;" : "+l"(acc) : "l"(d));
}

// One block per batch. 512 threads = 16 warps; warp w owns the 16 consecutive
// lags 16w+1 .. 16w+16 over ALL positions. Each lane handles 2 consecutive
// positions per iteration: 1 start v2.b64 + 9 end v2.b64 (18-value window,
// 16B-aligned because ebase = lag0-1 is even) cover 32 pairs/lane — all loads
// contiguous across lanes => conflict-free, ~5 B/pair of smem traffic.
// MSD results go to SHARED memory; the fit runs in-block after one barrier.
__global__ __launch_bounds__(NT) void physics_kernel(
    const float* __restrict__ traj,
    const float* __restrict__ alpha_pred,
    const int* __restrict__ lengths,
    float* __restrict__ out)
{
    __shared__ __align__(16) float2 s[TT + 2];
    __shared__ float sS[MAXLAG];
    __shared__ float sh[16];
    __shared__ int flag_all;

    const int b = blockIdx.x;
    const float2* tr = reinterpret_cast<const float2*>(traj) + (size_t)b * TT;
    for (int i = threadIdx.x; i < TT; i += NT) s[i] = tr[i];
    __syncthreads();

    const int L    = lengths[b];
    const int w    = threadIdx.x >> 5;
    const int lane = threadIdx.x & 31;

    // ---- MSD phase ----
    const int lag0 = 16 * w + 1;                 // lags lag0 .. lag0+15
    int np0  = L - lag0;  if (np0  < 0) np0  = 0;   // positions for smallest lag
    int np15 = np0 - 15;  if (np15 < 0) np15 = 0;   // positions for largest lag
    const int K = np15 >> 6;                     // unguarded 64-position rounds

    const unsigned sbase  = (unsigned)__cvta_generic_to_shared(s);
    unsigned addr_a = sbase + 16u * (unsigned)lane;
    unsigned addr_e = sbase + (((unsigned)(lag0 - 1)) << 3) + 16u * (unsigned)lane;
    const unsigned long long NEG1 = 0xBF800000BF800000ULL;   // {-1.f,-1.f}

    unsigned long long acc[16];
#pragma unroll
    for (int k = 0; k < 16; ++k) acc[k] = 0ull;

    for (int t = 0; t < K; ++t) {
        unsigned long long a0, a1, ev[18];
        asm("ld.shared.v2.b64 {%0,%1}, [%2];" : "=l"(a0), "=l"(a1) : "r"(addr_a));
#pragma unroll
        for (int j = 0; j < 9; ++j)
            asm("ld.shared.v2.b64 {%0,%1}, [%2];"
                : "=l"(ev[2 * j]), "=l"(ev[2 * j + 1])
                : "r"(addr_e + 16u * (unsigned)j));
#pragma unroll
        for (int k = 0; k < 16; ++k) {
            step2(acc[k], a0, ev[k + 1], NEG1);   // pair (p0,   lag0+k)
            step2(acc[k], a1, ev[k + 2], NEG1);   // pair (p0+1, lag0+k)
        }
        addr_a += 512;    // 64 positions * 8 B
        addr_e += 512;
    }

    float f[16];
#pragma unroll
    for (int k = 0; k < 16; ++k)
        f[k] = __uint_as_float((unsigned)acc[k]) +
               __uint_as_float((unsigned)(acc[k] >> 32));

    // Guarded tail: positions [64K, np0), at most ~3 rounds of 32.
    for (int p = (K << 6) + lane; p < np0; p += 32) {
        const float2 a = s[p];
#pragma unroll
        for (int k = 0; k < 16; ++k) {
            if (p < np0 - k) {
                const float2 e = s[p + lag0 + k];
                const float dx = e.x - a.x, dy = e.y - a.y;
                f[k] = fmaf(dx, dx, f[k]);
                f[k] = fmaf(dy, dy, f[k]);
            }
        }
    }

#pragma unroll
    for (int k = 0; k < 16; ++k) {
#pragma unroll
        for (int o = 16; o; o >>= 1)
            f[k] += __shfl_xor_sync(0xffffffffu, f[k], o);
    }
    if (lane == 0) {
#pragma unroll
        for (int k = 0; k < 16; ++k) sS[16 * w + k] = f[k];
    }
    __syncthreads();

    // ---- in-block fit (threads 0..255; one thread per lag) ----
    const float alpha = alpha_pred[b];
    float resid = 0.f, m = 0.f;
    if (threadIdx.x < MAXLAG) {
        const int il  = threadIdx.x;
        const int lag = il + 1;
        const int np  = L - lag;
        const int cnt = (np > 0) ? np : 1;          // counts = max(#valid, 1)
        const float lm = logf(sS[il] / (float)cnt + 1e-8f);
        const float ll = logf((float)lag);
        m     = (L > lag) ? 1.f : 0.f;
        resid = lm - alpha * ll;
    }

    // reduction 1: sum(resid*m), sum(m)   (warps 8..15 contribute zeros)
    float sr = resid * m, sm = m;
#pragma unroll
    for (int o = 16; o; o >>= 1) {
        sr += __shfl_xor_sync(0xffffffffu, sr, o);
        sm += __shfl_xor_sync(0xffffffffu, sm, o);
    }
    if (lane == 0 && w < 8) { sh[w] = sr; sh[8 + w] = sm; }
    __syncthreads();
    float srt = 0.f, smt = 0.f;
#pragma unroll
    for (int k = 0; k < 8; ++k) { srt += sh[k]; smt += sh[8 + k]; }

    const float denom     = (smt > 1.f) ? smt : 1.f;
    const float intercept = srt / denom;

    // reduction 2: sum((intercept - resid)^2 * m)
    const float dd = (intercept - resid) * m;
    float se = dd * dd;
#pragma unroll
    for (int o = 16; o; o >>= 1) se += __shfl_xor_sync(0xffffffffu, se, o);
    __syncthreads();
    if (lane == 0 && w < 8) sh[w] = se;
    __syncthreads();

    if (threadIdx.x == 0) {
        float t = 0.f;
#pragma unroll
        for (int k = 0; k < 8; ++k) t += sh[k];
        g_P[b] = t / denom;
        __threadfence();                 // publish g_P[b] (1 thread only)
        flag_all = (atomicAdd(&g_done, 1) == BB - 1) ? 1 : 0;
    }
    __syncthreads();
    if (!flag_all) return;

    // ---- globally-last block: mean over batches ----
    if (threadIdx.x < 32) {
        __threadfence();                 // acquire side
        const volatile float* vp = g_P;
        float t = vp[threadIdx.x] + vp[threadIdx.x + 32];
#pragma unroll
        for (int o = 16; o; o >>= 1) t += __shfl_xor_sync(0xffffffffu, t, o);
        if (threadIdx.x == 0) {
            out[0] = t / (float)BB;
            g_done = 0;                  // reset for next graph replay
        }
    }
}

extern "C" void kernel_launch(void* const* d_in, const int* in_sizes, int n_in,
                              void* d_out, int out_size)
{
    const float* alpha_pred = (const float*)d_in[0];
    const float* trajectory = (const float*)d_in[1];
    const int*   lengths    = (const int*)d_in[2];
    float* out = (float*)d_out;

    physics_kernel<<<BB, NT>>>(trajectory, alpha_pred, lengths, out);
}